// round 7
// baseline (speedup 1.0000x reference)
#include <cuda_runtime.h>
#include <cuda_bf16.h>
#include <cstdint>

#define B_    2
#define S_    2048
#define HID_  4096
#define NH_   32
#define NKV_  8
#define HD_   128

// ---------------------------------------------------------------------------
// Scratch
// ---------------------------------------------------------------------------
__device__ float g_Q[(size_t)B_ * NH_ * S_ * HD_];
__device__ float g_K[(size_t)B_ * NKV_ * S_ * HD_];
__device__ float g_V[(size_t)B_ * NKV_ * S_ * HD_];
__device__ float g_ctx[(size_t)B_ * S_ * HID_];

// bf16 hi/lo split operands for tensor-core GEMMs
__device__ __nv_bfloat16 g_hidh[(size_t)B_ * S_ * HID_];
__device__ __nv_bfloat16 g_hidl[(size_t)B_ * S_ * HID_];
__device__ __nv_bfloat16 g_Wqh[(size_t)HID_ * HID_];
__device__ __nv_bfloat16 g_Wql[(size_t)HID_ * HID_];
__device__ __nv_bfloat16 g_Wkvh[(size_t)2 * NKV_ * HD_ * HID_];
__device__ __nv_bfloat16 g_Wkvl[(size_t)2 * NKV_ * HD_ * HID_];
__device__ __nv_bfloat16 g_Wdh[(size_t)HID_ * HID_];
__device__ __nv_bfloat16 g_Wdl[(size_t)HID_ * HID_];
__device__ __nv_bfloat16 g_ctxh[(size_t)B_ * S_ * HID_];
__device__ __nv_bfloat16 g_ctxl[(size_t)B_ * S_ * HID_];

// ---------------------------------------------------------------------------
// fp32 -> (hi, lo) bf16 split. sel chooses destination globals.
// sel: 0=hidden, 1=Wq, 2=Wkv, 3=Wd, 4=ctx (src ignored, reads g_ctx)
// ---------------------------------------------------------------------------
__global__ void split_sel(const float* __restrict__ src, int sel, int n4)
{
    int i = blockIdx.x * blockDim.x + threadIdx.x;
    if (i >= n4) return;
    __nv_bfloat16 *hi, *lo;
    const float* s = src;
    if      (sel == 0) { hi = g_hidh; lo = g_hidl; }
    else if (sel == 1) { hi = g_Wqh;  lo = g_Wql;  }
    else if (sel == 2) { hi = g_Wkvh; lo = g_Wkvl; }
    else if (sel == 3) { hi = g_Wdh;  lo = g_Wdl;  }
    else               { hi = g_ctxh; lo = g_ctxl; s = g_ctx; }

    float4 v = ((const float4*)s)[i];
    float vv[4] = {v.x, v.y, v.z, v.w};
    __align__(8) __nv_bfloat16 h[4], l[4];
#pragma unroll
    for (int j = 0; j < 4; j++) {
        h[j] = __float2bfloat16_rn(vv[j]);
        l[j] = __float2bfloat16_rn(vv[j] - __bfloat162float(h[j]));
    }
    ((uint2*)hi)[i] = *(const uint2*)h;
    ((uint2*)lo)[i] = *(const uint2*)l;
}

// ---------------------------------------------------------------------------
// Tensor-core GEMM with bf16 hi/lo split (3 mma passes):
//   C = Ahi*Bhi^T + Ahi*Blo^T + Alo*Bhi^T   (fp32 accumulate)
// A: [M][K] row-major bf16, B(=W): [N][K] row-major bf16 (k-contiguous = "col")
// Block 128x128, BK=32, 256 thr (8 warps 2x4, warp tile 64x32, 4x4 m16n8k16)
// smem: 2 buffers x 4 arrays x 128 rows x 40 halves (pad-40 -> conflict-free
// ldmatrix phases). cp.async double-buffered mainloop.
// ---------------------------------------------------------------------------
#define SKS    40
#define TILE_H (128 * SKS)
#define GSMEM  (2 * 4 * TILE_H * 2)

__device__ __forceinline__ uint32_t smem_u32(const void* p) {
    return (uint32_t)__cvta_generic_to_shared(p);
}
__device__ __forceinline__ void ldsm_x4(uint32_t* r, uint32_t a) {
    asm volatile("ldmatrix.sync.aligned.m8n8.x4.shared.b16 {%0,%1,%2,%3}, [%4];\n"
        : "=r"(r[0]), "=r"(r[1]), "=r"(r[2]), "=r"(r[3]) : "r"(a));
}
__device__ __forceinline__ void mma16816(float* d, const uint32_t* a, const uint32_t* b) {
    asm volatile("mma.sync.aligned.m16n8k16.row.col.f32.bf16.bf16.f32 "
        "{%0,%1,%2,%3}, {%4,%5,%6,%7}, {%8,%9}, {%0,%1,%2,%3};\n"
        : "+f"(d[0]), "+f"(d[1]), "+f"(d[2]), "+f"(d[3])
        : "r"(a[0]), "r"(a[1]), "r"(a[2]), "r"(a[3]), "r"(b[0]), "r"(b[1]));
}
__device__ __forceinline__ void cp16(uint32_t s, const void* g) {
    asm volatile("cp.async.cg.shared.global [%0], [%1], 16;\n" :: "r"(s), "l"(g));
}
__device__ __forceinline__ void cp_commit() {
    asm volatile("cp.async.commit_group;\n");
}
__device__ __forceinline__ void cp_wait0() {
    asm volatile("cp.async.wait_group 0;\n");
}

template <int MODE>
__global__ __launch_bounds__(256)
void gemm3(const float* __restrict__ bias, float* __restrict__ out)
{
    const __nv_bfloat16 *Ahi, *Alo, *Bhi, *Blo;
    if (MODE == 0)      { Ahi = g_hidh; Alo = g_hidl; Bhi = g_Wqh;  Blo = g_Wql;  }
    else if (MODE == 1) { Ahi = g_hidh; Alo = g_hidl; Bhi = g_Wkvh; Blo = g_Wkvl; }
    else                { Ahi = g_ctxh; Alo = g_ctxl; Bhi = g_Wdh;  Blo = g_Wdl;  }

    extern __shared__ __align__(16) __nv_bfloat16 sh[];
    const int K = HID_;
    const int tid  = threadIdx.x;
    const int lane = tid & 31, wid = tid >> 5;
    const int wm = wid >> 2, wn = wid & 3;
    const int bm = blockIdx.y, bn = blockIdx.x;

    // global->smem load mapping: (row = tid&63 [+64], chunk = tid>>6 of 8 halves)
    const int lrow = tid & 63;
    const int lch  = tid >> 6;
    const __nv_bfloat16* gsrc[4] = {
        Ahi + (size_t)(bm * 128 + lrow) * K + lch * 8,
        Alo + (size_t)(bm * 128 + lrow) * K + lch * 8,
        Bhi + (size_t)(bn * 128 + lrow) * K + lch * 8,
        Blo + (size_t)(bn * 128 + lrow) * K + lch * 8 };
    uint32_t sw[4];
#pragma unroll
    for (int a = 0; a < 4; a++)
        sw[a] = smem_u32(sh + a * TILE_H + lrow * SKS + lch * 8);
    const uint32_t bufBytes = 4 * TILE_H * 2;

    float acc[4][4][4];
#pragma unroll
    for (int mt = 0; mt < 4; mt++)
#pragma unroll
        for (int nt = 0; nt < 4; nt++)
#pragma unroll
            for (int e = 0; e < 4; e++) acc[mt][nt][e] = 0.f;

    // prologue: tile 0 -> buffer 0
#pragma unroll
    for (int a = 0; a < 4; a++) {
        cp16(sw[a], gsrc[a]);
        cp16(sw[a] + 64 * SKS * 2, gsrc[a] + (size_t)64 * K);
    }
    cp_commit();
    cp_wait0();
    __syncthreads();

    const int nkt = K / 32;
    for (int kt = 0; kt < nkt; kt++) {
        const int buf = kt & 1;
        if (kt + 1 < nkt) {
            const uint32_t bo = (buf ^ 1) * bufBytes;
            const int go = (kt + 1) * 32;
#pragma unroll
            for (int a = 0; a < 4; a++) {
                cp16(sw[a] + bo, gsrc[a] + go);
                cp16(sw[a] + bo + 64 * SKS * 2, gsrc[a] + (size_t)64 * K + go);
            }
            cp_commit();
        }

        const __nv_bfloat16* base = sh + buf * 4 * TILE_H;
        const __nv_bfloat16* pAhi = base;
        const __nv_bfloat16* pAlo = base + TILE_H;
        const __nv_bfloat16* pBhi = base + 2 * TILE_H;
        const __nv_bfloat16* pBlo = base + 3 * TILE_H;

#pragma unroll
        for (int ks = 0; ks < 2; ks++) {
            const int col = ks * 16 + (lane >> 4) * 8;
            uint32_t ahi[4][4], alo[4][4];
#pragma unroll
            for (int mt = 0; mt < 4; mt++) {
                const int row = wm * 64 + mt * 16 + (lane & 15);
                ldsm_x4(ahi[mt], smem_u32(pAhi + row * SKS + col));
                ldsm_x4(alo[mt], smem_u32(pAlo + row * SKS + col));
            }
            uint32_t bhi[4][2], blo[4][2];
#pragma unroll
            for (int g = 0; g < 2; g++) {
                const int row = wn * 32 + g * 16 + (lane & 15);
                uint32_t t[4];
                ldsm_x4(t, smem_u32(pBhi + row * SKS + col));
                bhi[2 * g][0] = t[0]; bhi[2 * g][1] = t[2];
                bhi[2 * g + 1][0] = t[1]; bhi[2 * g + 1][1] = t[3];
                ldsm_x4(t, smem_u32(pBlo + row * SKS + col));
                blo[2 * g][0] = t[0]; blo[2 * g][1] = t[2];
                blo[2 * g + 1][0] = t[1]; blo[2 * g + 1][1] = t[3];
            }
#pragma unroll
            for (int mt = 0; mt < 4; mt++)
#pragma unroll
                for (int nt = 0; nt < 4; nt++) {
                    mma16816(acc[mt][nt], ahi[mt], bhi[nt]);
                    mma16816(acc[mt][nt], ahi[mt], blo[nt]);
                    mma16816(acc[mt][nt], alo[mt], bhi[nt]);
                }
        }

        if (kt + 1 < nkt) cp_wait0();
        __syncthreads();
    }

    // epilogue: m16n8 C frag: (c0,c1)=(r, c),(r, c+1); (c2,c3)=(r+8, ...)
    const int r0 = lane >> 2, c0 = (lane & 3) * 2;
#pragma unroll
    for (int mt = 0; mt < 4; mt++)
#pragma unroll
        for (int nt = 0; nt < 4; nt++)
#pragma unroll
            for (int e = 0; e < 4; e++) {
                const int m = bm * 128 + wm * 64 + mt * 16 + r0 + ((e >> 1) ? 8 : 0);
                const int n = bn * 128 + wn * 32 + nt * 8 + c0 + (e & 1);
                const float v = acc[mt][nt][e];
                if (MODE == 0) {
                    const int bb = m >> 11, s = m & (S_ - 1);
                    const int h = n >> 7, d = n & 127;
                    g_Q[(((size_t)bb * NH_ + h) * S_ + s) * HD_ + d] = v;
                } else if (MODE == 1) {
                    const int bb = m >> 11, s = m & (S_ - 1);
                    const int kvh = n >> 8, jj = n & 255;
                    if (jj < 128)
                        g_K[(((size_t)bb * NKV_ + kvh) * S_ + s) * HD_ + jj] = v;
                    else
                        g_V[(((size_t)bb * NKV_ + kvh) * S_ + s) * HD_ + (jj - 128)] = v;
                } else {
                    out[(size_t)m * HID_ + n] = v + bias[n];
                }
            }
}

// ---------------------------------------------------------------------------
// RoPE in place on g_Q, g_K (cos/sin identical for d and d+64)
// ---------------------------------------------------------------------------
__global__ void rope_kernel(const float* __restrict__ cosT,
                            const float* __restrict__ sinT)
{
    const int qPairs = B_ * NH_ * S_ * (HD_ / 2);
    const int tPairs = qPairs + B_ * NKV_ * S_ * (HD_ / 2);
    int idx = blockIdx.x * blockDim.x + threadIdx.x;
    if (idx >= tPairs) return;
    float* base;
    int li;
    if (idx < qPairs) { li = idx; base = g_Q; }
    else              { li = idx - qPairs; base = g_K; }
    const int dp = li & 63;
    const int s = (li >> 6) & (S_ - 1);
    const int bh = li >> 17;
    const float c = cosT[s * HD_ + dp];
    const float sn = sinT[s * HD_ + dp];
    float* p = base + ((size_t)bh * S_ + s) * HD_;
    const float x1 = p[dp], x2 = p[dp + 64];
    p[dp]      = x1 * c - x2 * sn;
    p[dp + 64] = x2 * c + x1 * sn;
}

// ---------------------------------------------------------------------------
// Causal flash attention, fp32 (unchanged from R4 passing version)
// ---------------------------------------------------------------------------
#define ATTN_SMEM_FLOATS (128 * 68 * 2 + 64 * 128 + 64 * 68)
#define ATTN_SMEM_BYTES  (ATTN_SMEM_FLOATS * 4)

__global__ __launch_bounds__(256)
void attn_kernel()
{
    extern __shared__ float sm[];
    float* sQt = sm;
    float* sKt = sm + 128 * 68;
    float* sV  = sKt + 128 * 68;
    float* sPt = sV + 64 * 128;

    const int qt = blockIdx.x;
    const int h  = blockIdx.y;
    const int b  = blockIdx.z;
    const int kvh = h >> 2;
    const int tid = threadIdx.x;
    const int ty = tid >> 4, tx = tid & 15;

    const float* Qg = g_Q + (((size_t)b * NH_ + h) * S_ + qt * 64) * HD_;
    const float* Kb = g_K + ((size_t)b * NKV_ + kvh) * S_ * HD_;
    const float* Vb = g_V + ((size_t)b * NKV_ + kvh) * S_ * HD_;

#pragma unroll
    for (int it = 0; it < 8; it++) {
        const int f = tid + it * 256;
        const int r = f >> 5;
        const int d4 = (f & 31) * 4;
        const float4 v = *(const float4*)(Qg + (size_t)r * HD_ + d4);
        sQt[(d4 + 0) * 68 + r] = v.x;
        sQt[(d4 + 1) * 68 + r] = v.y;
        sQt[(d4 + 2) * 68 + r] = v.z;
        sQt[(d4 + 3) * 68 + r] = v.w;
    }

    float mi[4], li[4], O[4][8];
#pragma unroll
    for (int i = 0; i < 4; i++) {
        mi[i] = -1e30f; li[i] = 0.f;
#pragma unroll
        for (int j = 0; j < 8; j++) O[i][j] = 0.f;
    }

    const float scale = 0.08838834764831845f;
    const int nkt = qt + 1;

    for (int kt = 0; kt < nkt; kt++) {
        __syncthreads();
        const float* Kg = Kb + (size_t)kt * 64 * HD_;
        const float* Vg = Vb + (size_t)kt * 64 * HD_;
#pragma unroll
        for (int it = 0; it < 8; it++) {
            const int f = tid + it * 256;
            const int r = f >> 5;
            const int d4 = (f & 31) * 4;
            const float4 kv = *(const float4*)(Kg + (size_t)r * HD_ + d4);
            sKt[(d4 + 0) * 68 + r] = kv.x;
            sKt[(d4 + 1) * 68 + r] = kv.y;
            sKt[(d4 + 2) * 68 + r] = kv.z;
            sKt[(d4 + 3) * 68 + r] = kv.w;
            *(float4*)&sV[r * 128 + d4] = *(const float4*)(Vg + (size_t)r * HD_ + d4);
        }
        __syncthreads();

        float sacc[4][4];
#pragma unroll
        for (int i = 0; i < 4; i++)
#pragma unroll
            for (int j = 0; j < 4; j++) sacc[i][j] = 0.f;

#pragma unroll 8
        for (int d = 0; d < 128; d++) {
            const float4 a = *(const float4*)&sQt[d * 68 + ty * 4];
            const float4 kk = *(const float4*)&sKt[d * 68 + tx * 4];
            const float av[4] = {a.x, a.y, a.z, a.w};
            const float kv2[4] = {kk.x, kk.y, kk.z, kk.w};
#pragma unroll
            for (int i = 0; i < 4; i++)
#pragma unroll
                for (int j = 0; j < 4; j++)
                    sacc[i][j] = fmaf(av[i], kv2[j], sacc[i][j]);
        }

        const int rq0 = qt * 64 + ty * 4;
        const int ck0 = kt * 64 + tx * 4;
        float corr[4];
#pragma unroll
        for (int i = 0; i < 4; i++) {
            float sv[4];
#pragma unroll
            for (int j = 0; j < 4; j++)
                sv[j] = (ck0 + j <= rq0 + i) ? sacc[i][j] * scale : -1e30f;
            float rm = fmaxf(fmaxf(sv[0], sv[1]), fmaxf(sv[2], sv[3]));
#pragma unroll
            for (int msk = 8; msk; msk >>= 1)
                rm = fmaxf(rm, __shfl_xor_sync(0xffffffffu, rm, msk, 16));
            const float newm = fmaxf(mi[i], rm);
            corr[i] = __expf(mi[i] - newm);
            float rs = 0.f;
#pragma unroll
            for (int j = 0; j < 4; j++) {
                const float pz = __expf(sv[j] - newm);
                rs += pz;
                sPt[(tx * 4 + j) * 68 + ty * 4 + i] = pz;
            }
#pragma unroll
            for (int msk = 8; msk; msk >>= 1)
                rs += __shfl_xor_sync(0xffffffffu, rs, msk, 16);
            li[i] = li[i] * corr[i] + rs;
            mi[i] = newm;
        }
        __syncthreads();

#pragma unroll
        for (int i = 0; i < 4; i++)
#pragma unroll
            for (int j = 0; j < 8; j++) O[i][j] *= corr[i];

#pragma unroll 4
        for (int c = 0; c < 64; c++) {
            const float4 p = *(const float4*)&sPt[c * 68 + ty * 4];
            const float4 v0 = *(const float4*)&sV[c * 128 + tx * 4];
            const float4 v1 = *(const float4*)&sV[c * 128 + 64 + tx * 4];
            const float pv[4] = {p.x, p.y, p.z, p.w};
            const float va[8] = {v0.x, v0.y, v0.z, v0.w, v1.x, v1.y, v1.z, v1.w};
#pragma unroll
            for (int i = 0; i < 4; i++)
#pragma unroll
                for (int j = 0; j < 8; j++)
                    O[i][j] = fmaf(pv[i], va[j], O[i][j]);
        }
    }

#pragma unroll
    for (int i = 0; i < 4; i++) {
        const float inv = 1.f / li[i];
        const int srow = qt * 64 + ty * 4 + i;
        float* dst = g_ctx + ((size_t)b * S_ + srow) * HID_ + h * HD_;
#pragma unroll
        for (int j = 0; j < 4; j++) dst[tx * 4 + j] = O[i][j] * inv;
#pragma unroll
        for (int j = 0; j < 4; j++) dst[64 + tx * 4 + j] = O[i][j + 4] * inv;
    }
}

// ---------------------------------------------------------------------------
// Inputs: hidden_states, attention_mask(unused, analytic causal), cos, sin,
//         Wq, Wkv, Wd, bd
// ---------------------------------------------------------------------------
extern "C" void kernel_launch(void* const* d_in, const int* in_sizes, int n_in,
                              void* d_out, int out_size)
{
    (void)in_sizes; (void)n_in; (void)out_size;
    const float* hidden = (const float*)d_in[0];
    const float* cosT   = (const float*)d_in[2];
    const float* sinT   = (const float*)d_in[3];
    const float* Wq     = (const float*)d_in[4];
    const float* Wkv    = (const float*)d_in[5];
    const float* Wd     = (const float*)d_in[6];
    const float* bd     = (const float*)d_in[7];
    float* out = (float*)d_out;

    cudaFuncSetAttribute(attn_kernel,
                         cudaFuncAttributeMaxDynamicSharedMemorySize, ATTN_SMEM_BYTES);
    cudaFuncSetAttribute(gemm3<0>,
                         cudaFuncAttributeMaxDynamicSharedMemorySize, GSMEM);
    cudaFuncSetAttribute(gemm3<1>,
                         cudaFuncAttributeMaxDynamicSharedMemorySize, GSMEM);
    cudaFuncSetAttribute(gemm3<2>,
                         cudaFuncAttributeMaxDynamicSharedMemorySize, GSMEM);

    const int M = B_ * S_;

    // hi/lo splits of hidden + weights
    {
        int n4 = (B_ * S_ * HID_) / 4;
        split_sel<<<(n4 + 255) / 256, 256>>>(hidden, 0, n4);
        n4 = (HID_ * HID_) / 4;
        split_sel<<<(n4 + 255) / 256, 256>>>(Wq, 1, n4);
        n4 = (2 * NKV_ * HD_ * HID_) / 4;
        split_sel<<<(n4 + 255) / 256, 256>>>(Wkv, 2, n4);
        n4 = (HID_ * HID_) / 4;
        split_sel<<<(n4 + 255) / 256, 256>>>(Wd, 3, n4);
    }

    gemm3<0><<<dim3(HID_ / 128, M / 128), 256, GSMEM>>>(nullptr, nullptr);
    gemm3<1><<<dim3((2 * NKV_ * HD_) / 128, M / 128), 256, GSMEM>>>(nullptr, nullptr);

    const int totalPairs = B_ * NH_ * S_ * (HD_ / 2) + B_ * NKV_ * S_ * (HD_ / 2);
    rope_kernel<<<(totalPairs + 255) / 256, 256>>>(cosT, sinT);

    attn_kernel<<<dim3(S_ / 64, NH_, B_), 256, ATTN_SMEM_BYTES>>>();

    {
        const int n4 = (B_ * S_ * HID_) / 4;
        split_sel<<<(n4 + 255) / 256, 256>>>(nullptr, 4, n4);
    }
    gemm3<2><<<dim3(HID_ / 128, M / 128), 256, GSMEM>>>(bd, out);
}

// round 13
// speedup vs baseline: 2.0637x; 2.0637x over previous
#include <cuda_runtime.h>
#include <cuda_fp16.h>
#include <cstdint>

#define B_    2
#define S_    2048
#define HID_  4096
#define NH_   32
#define NKV_  8
#define HD_   128

// ---------------------------------------------------------------------------
// Scratch
// ---------------------------------------------------------------------------
__device__ float g_Q[(size_t)B_ * NH_ * S_ * HD_];
__device__ float g_K[(size_t)B_ * NKV_ * S_ * HD_];
__device__ float g_V[(size_t)B_ * NKV_ * S_ * HD_];
__device__ float g_ctx[(size_t)B_ * S_ * HID_];

// fp16 operands for mma.sync GEMMs
__device__ __align__(256) __half g_hidh[(size_t)B_ * S_ * HID_];
__device__ __align__(256) __half g_hidl[(size_t)B_ * S_ * HID_];
__device__ __align__(256) __half g_Wqh[(size_t)HID_ * HID_];
__device__ __align__(256) __half g_Wql[(size_t)HID_ * HID_];
__device__ __align__(256) __half g_Wkvh[(size_t)2 * NKV_ * HD_ * HID_];
__device__ __align__(256) __half g_Wkvl[(size_t)2 * NKV_ * HD_ * HID_];
__device__ __align__(256) __half g_Wdh[(size_t)HID_ * HID_];
__device__ __align__(256) __half g_ctxh[(size_t)B_ * S_ * HID_];

// ---------------------------------------------------------------------------
// helpers
// ---------------------------------------------------------------------------
__device__ __forceinline__ uint32_t smem_u32(const void* p) {
    return (uint32_t)__cvta_generic_to_shared(p);
}
__device__ __forceinline__ void cp16(uint32_t s, const void* g) {
    asm volatile("cp.async.cg.shared.global [%0], [%1], 16;\n" :: "r"(s), "l"(g));
}
__device__ __forceinline__ void cp_commit() { asm volatile("cp.async.commit_group;\n"); }
template <int N>
__device__ __forceinline__ void cp_wait() {
    asm volatile("cp.async.wait_group %0;\n" :: "n"(N));
}
__device__ __forceinline__ void ldsm_x4(uint32_t* r, uint32_t a) {
    asm volatile("ldmatrix.sync.aligned.m8n8.x4.shared.b16 {%0,%1,%2,%3}, [%4];\n"
        : "=r"(r[0]), "=r"(r[1]), "=r"(r[2]), "=r"(r[3]) : "r"(a));
}
__device__ __forceinline__ void mma_h(float* d, const uint32_t* a, const uint32_t* b) {
    asm volatile("mma.sync.aligned.m16n8k16.row.col.f32.f16.f16.f32 "
        "{%0,%1,%2,%3}, {%4,%5,%6,%7}, {%8,%9}, {%0,%1,%2,%3};\n"
        : "+f"(d[0]), "+f"(d[1]), "+f"(d[2]), "+f"(d[3])
        : "r"(a[0]), "r"(a[1]), "r"(a[2]), "r"(a[3]), "r"(b[0]), "r"(b[1]));
}

// ---------------------------------------------------------------------------
// splits: fp32 -> fp16 hi (+ lo residual)
// split2_sel: sel 0=hidden, 1=Wq, 2=Wkv  (hi+lo)
// split1_sel: sel 0=Wd, 1=ctx(g_ctx)     (hi only)
// ---------------------------------------------------------------------------
__global__ void split2_sel(const float* __restrict__ src, int sel, int n4)
{
    int i = blockIdx.x * blockDim.x + threadIdx.x;
    if (i >= n4) return;
    __half *hi, *lo;
    if      (sel == 0) { hi = g_hidh; lo = g_hidl; }
    else if (sel == 1) { hi = g_Wqh;  lo = g_Wql;  }
    else               { hi = g_Wkvh; lo = g_Wkvl; }
    float4 v = ((const float4*)src)[i];
    float vv[4] = {v.x, v.y, v.z, v.w};
    __align__(8) __half h[4], l[4];
#pragma unroll
    for (int j = 0; j < 4; j++) {
        h[j] = __float2half_rn(vv[j]);
        l[j] = __float2half_rn(vv[j] - __half2float(h[j]));
    }
    ((uint2*)hi)[i] = *(const uint2*)h;
    ((uint2*)lo)[i] = *(const uint2*)l;
}

__global__ void split1_sel(const float* __restrict__ src, int sel, int n4)
{
    int i = blockIdx.x * blockDim.x + threadIdx.x;
    if (i >= n4) return;
    __half* hi = (sel == 0) ? g_Wdh : g_ctxh;
    const float* s = (sel == 0) ? src : g_ctx;
    float4 v = ((const float4*)s)[i];
    float vv[4] = {v.x, v.y, v.z, v.w};
    __align__(8) __half h[4];
#pragma unroll
    for (int j = 0; j < 4; j++) h[j] = __float2half_rn(vv[j]);
    ((uint2*)hi)[i] = *(const uint2*)h;
}

// ---------------------------------------------------------------------------
// gemm_h3: fp16 hi/lo 3-pass mma.sync GEMM, C = A @ W^T (fp32 accum)
// Block 128x128, BK=32, 256 thr (8 warps 2x4: warp tile 64x32), 3-stage
// cp.async pipeline. MODE 0 -> g_Q scatter, MODE 1 -> g_K/g_V scatter.
// smem per stage: {Ah, Al, Bh, Bl} x 128 rows x 40 halves (pad-40).
// ---------------------------------------------------------------------------
#define SKS   40
#define ARRB  (128 * SKS * 2)       // 10240 B per array per stage
#define STG3  (4 * ARRB)            // 40960 B
#define SM3   (3 * STG3)            // 122880 B
#define STG1  (2 * ARRB)            // 20480 B
#define SM1   (4 * STG1)            // 81920 B

template <int MODE>
__global__ __launch_bounds__(256)
void gemm_h3()
{
    const __half *Ah, *Al, *Bh, *Bl;
    if (MODE == 0) { Ah = g_hidh; Al = g_hidl; Bh = g_Wqh;  Bl = g_Wql;  }
    else           { Ah = g_hidh; Al = g_hidl; Bh = g_Wkvh; Bl = g_Wkvl; }

    extern __shared__ __align__(16) __half sh[];
    const uint32_t sb = smem_u32(sh);
    const int K = HID_;
    const int tid = threadIdx.x, wid = tid >> 5, lane = tid & 31;
    const int wm = wid >> 2, wn = wid & 3;
    const int bm = blockIdx.y, bn = blockIdx.x;

    // loader: 512 16B-granules per array per stage; 2 per thread
    uint32_t soff[2];
    size_t gA[2], gB[2];
#pragma unroll
    for (int i = 0; i < 2; i++) {
        const int gr = tid + i * 256;
        const int r = gr >> 2, c = gr & 3;
        soff[i] = (uint32_t)(r * SKS * 2 + c * 16);
        gA[i] = (size_t)(bm * 128 + r) * K + c * 8;
        gB[i] = (size_t)(bn * 128 + r) * K + c * 8;
    }

    auto load_stage = [&](int kt, int st) {
        const uint32_t b0 = sb + st * STG3;
        const size_t ko = (size_t)kt * 32;
#pragma unroll
        for (int i = 0; i < 2; i++) {
            cp16(b0 + 0 * ARRB + soff[i], Ah + gA[i] + ko);
            cp16(b0 + 1 * ARRB + soff[i], Al + gA[i] + ko);
            cp16(b0 + 2 * ARRB + soff[i], Bh + gB[i] + ko);
            cp16(b0 + 3 * ARRB + soff[i], Bl + gB[i] + ko);
        }
        cp_commit();
    };

    float acc[4][4][4];
#pragma unroll
    for (int mt = 0; mt < 4; mt++)
#pragma unroll
        for (int nt = 0; nt < 4; nt++)
#pragma unroll
            for (int e = 0; e < 4; e++) acc[mt][nt][e] = 0.f;

    load_stage(0, 0);
    load_stage(1, 1);

    const int nkt = K / 32;     // 128
    for (int kt = 0; kt < nkt; kt++) {
        if (kt + 1 < nkt) cp_wait<1>(); else cp_wait<0>();
        __syncthreads();

        const __half* base = sh + (kt % 3) * (STG3 / 2);
        const __half* pAh = base;
        const __half* pAl = base + ARRB / 2;
        const __half* pBh = base + 2 * (ARRB / 2);
        const __half* pBl = base + 3 * (ARRB / 2);

#pragma unroll
        for (int ks = 0; ks < 2; ks++) {
            const int col = ks * 16 + (lane >> 4) * 8;
            uint32_t ah[4][4], al[4][4];
#pragma unroll
            for (int mt = 0; mt < 4; mt++) {
                const int row = wm * 64 + mt * 16 + (lane & 15);
                ldsm_x4(ah[mt], smem_u32(pAh + row * SKS + col));
                ldsm_x4(al[mt], smem_u32(pAl + row * SKS + col));
            }
            uint32_t bh[4][2], bl[4][2];
#pragma unroll
            for (int g = 0; g < 2; g++) {
                const int row = wn * 32 + g * 16 + (lane & 15);
                uint32_t t[4];
                ldsm_x4(t, smem_u32(pBh + row * SKS + col));
                bh[2 * g][0] = t[0]; bh[2 * g][1] = t[2];
                bh[2 * g + 1][0] = t[1]; bh[2 * g + 1][1] = t[3];
                ldsm_x4(t, smem_u32(pBl + row * SKS + col));
                bl[2 * g][0] = t[0]; bl[2 * g][1] = t[2];
                bl[2 * g + 1][0] = t[1]; bl[2 * g + 1][1] = t[3];
            }
#pragma unroll
            for (int mt = 0; mt < 4; mt++)
#pragma unroll
                for (int nt = 0; nt < 4; nt++) {
                    mma_h(acc[mt][nt], ah[mt], bh[nt]);
                    mma_h(acc[mt][nt], ah[mt], bl[nt]);
                    mma_h(acc[mt][nt], al[mt], bh[nt]);
                }
        }

        if (kt + 2 < nkt) load_stage(kt + 2, (kt + 2) % 3);
    }

    // epilogue scatter (validated in R7)
    const int r0 = lane >> 2, c0 = (lane & 3) * 2;
#pragma unroll
    for (int mt = 0; mt < 4; mt++)
#pragma unroll
        for (int nt = 0; nt < 4; nt++)
#pragma unroll
            for (int e = 0; e < 4; e++) {
                const int m = bm * 128 + wm * 64 + mt * 16 + r0 + ((e >> 1) ? 8 : 0);
                const int n = bn * 128 + wn * 32 + nt * 8 + c0 + (e & 1);
                const float v = acc[mt][nt][e];
                const int bb = m >> 11, s = m & (S_ - 1);
                if (MODE == 0) {
                    const int h = n >> 7, d = n & 127;
                    g_Q[(((size_t)bb * NH_ + h) * S_ + s) * HD_ + d] = v;
                } else {
                    const int kvh = n >> 8, jj = n & 255;
                    if (jj < 128)
                        g_K[(((size_t)bb * NKV_ + kvh) * S_ + s) * HD_ + jj] = v;
                    else
                        g_V[(((size_t)bb * NKV_ + kvh) * S_ + s) * HD_ + (jj - 128)] = v;
                }
            }
}

// ---------------------------------------------------------------------------
// gemm_h1: single-pass fp16 mma GEMM, out = ctx @ Wd^T + bias
// 4-stage cp.async pipeline, same tiles as gemm_h3.
// ---------------------------------------------------------------------------
__global__ __launch_bounds__(256)
void gemm_h1(const float* __restrict__ bias, float* __restrict__ out)
{
    const __half* Ah = g_ctxh;
    const __half* Bh = g_Wdh;

    extern __shared__ __align__(16) __half sh[];
    const uint32_t sb = smem_u32(sh);
    const int K = HID_;
    const int tid = threadIdx.x, wid = tid >> 5, lane = tid & 31;
    const int wm = wid >> 2, wn = wid & 3;
    const int bm = blockIdx.y, bn = blockIdx.x;

    uint32_t soff[2];
    size_t gA[2], gB[2];
#pragma unroll
    for (int i = 0; i < 2; i++) {
        const int gr = tid + i * 256;
        const int r = gr >> 2, c = gr & 3;
        soff[i] = (uint32_t)(r * SKS * 2 + c * 16);
        gA[i] = (size_t)(bm * 128 + r) * K + c * 8;
        gB[i] = (size_t)(bn * 128 + r) * K + c * 8;
    }

    auto load_stage = [&](int kt, int st) {
        const uint32_t b0 = sb + st * STG1;
        const size_t ko = (size_t)kt * 32;
#pragma unroll
        for (int i = 0; i < 2; i++) {
            cp16(b0 + soff[i], Ah + gA[i] + ko);
            cp16(b0 + ARRB + soff[i], Bh + gB[i] + ko);
        }
        cp_commit();
    };

    float acc[4][4][4];
#pragma unroll
    for (int mt = 0; mt < 4; mt++)
#pragma unroll
        for (int nt = 0; nt < 4; nt++)
#pragma unroll
            for (int e = 0; e < 4; e++) acc[mt][nt][e] = 0.f;

    load_stage(0, 0);
    load_stage(1, 1);
    load_stage(2, 2);

    const int nkt = K / 32;
    for (int kt = 0; kt < nkt; kt++) {
        if (kt + 2 < nkt)      cp_wait<2>();
        else if (kt + 1 < nkt) cp_wait<1>();
        else                   cp_wait<0>();
        __syncthreads();

        const __half* base = sh + (kt % 4) * (STG1 / 2);
        const __half* pAh = base;
        const __half* pBh = base + ARRB / 2;

#pragma unroll
        for (int ks = 0; ks < 2; ks++) {
            const int col = ks * 16 + (lane >> 4) * 8;
            uint32_t ah[4][4];
#pragma unroll
            for (int mt = 0; mt < 4; mt++) {
                const int row = wm * 64 + mt * 16 + (lane & 15);
                ldsm_x4(ah[mt], smem_u32(pAh + row * SKS + col));
            }
            uint32_t bh[4][2];
#pragma unroll
            for (int g = 0; g < 2; g++) {
                const int row = wn * 32 + g * 16 + (lane & 15);
                uint32_t t[4];
                ldsm_x4(t, smem_u32(pBh + row * SKS + col));
                bh[2 * g][0] = t[0]; bh[2 * g][1] = t[2];
                bh[2 * g + 1][0] = t[1]; bh[2 * g + 1][1] = t[3];
            }
#pragma unroll
            for (int mt = 0; mt < 4; mt++)
#pragma unroll
                for (int nt = 0; nt < 4; nt++)
                    mma_h(acc[mt][nt], ah[mt], bh[nt]);
        }

        if (kt + 3 < nkt) load_stage(kt + 3, (kt + 3) % 4);
    }

    const int r0 = lane >> 2, c0 = (lane & 3) * 2;
#pragma unroll
    for (int mt = 0; mt < 4; mt++)
#pragma unroll
        for (int nt = 0; nt < 4; nt++)
#pragma unroll
            for (int e = 0; e < 4; e++) {
                const int m = bm * 128 + wm * 64 + mt * 16 + r0 + ((e >> 1) ? 8 : 0);
                const int n = bn * 128 + wn * 32 + nt * 8 + c0 + (e & 1);
                out[(size_t)m * HID_ + n] = acc[mt][nt][e] + bias[n];
            }
}

// ---------------------------------------------------------------------------
// RoPE in place on g_Q, g_K
// ---------------------------------------------------------------------------
__global__ void rope_kernel(const float* __restrict__ cosT,
                            const float* __restrict__ sinT)
{
    const int qPairs = B_ * NH_ * S_ * (HD_ / 2);
    const int tPairs = qPairs + B_ * NKV_ * S_ * (HD_ / 2);
    int idx = blockIdx.x * blockDim.x + threadIdx.x;
    if (idx >= tPairs) return;
    float* base;
    int li;
    if (idx < qPairs) { li = idx; base = g_Q; }
    else              { li = idx - qPairs; base = g_K; }
    const int dp = li & 63;
    const int s = (li >> 6) & (S_ - 1);
    const int bh = li >> 17;
    const float c = cosT[s * HD_ + dp];
    const float sn = sinT[s * HD_ + dp];
    float* p = base + ((size_t)bh * S_ + s) * HD_;
    const float x1 = p[dp], x2 = p[dp + 64];
    p[dp]      = x1 * c - x2 * sn;
    p[dp + 64] = x2 * c + x1 * sn;
}

// ---------------------------------------------------------------------------
// Causal flash attention, fp32 (R4 passing version, unchanged)
// ---------------------------------------------------------------------------
#define ATTN_SMEM_FLOATS (128 * 68 * 2 + 64 * 128 + 64 * 68)
#define ATTN_SMEM_BYTES  (ATTN_SMEM_FLOATS * 4)

__global__ __launch_bounds__(256)
void attn_kernel()
{
    extern __shared__ float sm[];
    float* sQt = sm;
    float* sKt = sm + 128 * 68;
    float* sV  = sKt + 128 * 68;
    float* sPt = sV + 64 * 128;

    const int qt = blockIdx.x;
    const int h  = blockIdx.y;
    const int b  = blockIdx.z;
    const int kvh = h >> 2;
    const int tid = threadIdx.x;
    const int ty = tid >> 4, tx = tid & 15;

    const float* Qg = g_Q + (((size_t)b * NH_ + h) * S_ + qt * 64) * HD_;
    const float* Kb = g_K + ((size_t)b * NKV_ + kvh) * S_ * HD_;
    const float* Vb = g_V + ((size_t)b * NKV_ + kvh) * S_ * HD_;

#pragma unroll
    for (int it = 0; it < 8; it++) {
        const int f = tid + it * 256;
        const int r = f >> 5;
        const int d4 = (f & 31) * 4;
        const float4 v = *(const float4*)(Qg + (size_t)r * HD_ + d4);
        sQt[(d4 + 0) * 68 + r] = v.x;
        sQt[(d4 + 1) * 68 + r] = v.y;
        sQt[(d4 + 2) * 68 + r] = v.z;
        sQt[(d4 + 3) * 68 + r] = v.w;
    }

    float mi[4], li[4], O[4][8];
#pragma unroll
    for (int i = 0; i < 4; i++) {
        mi[i] = -1e30f; li[i] = 0.f;
#pragma unroll
        for (int j = 0; j < 8; j++) O[i][j] = 0.f;
    }

    const float scale = 0.08838834764831845f;
    const int nkt = qt + 1;

    for (int kt = 0; kt < nkt; kt++) {
        __syncthreads();
        const float* Kg = Kb + (size_t)kt * 64 * HD_;
        const float* Vg = Vb + (size_t)kt * 64 * HD_;
#pragma unroll
        for (int it = 0; it < 8; it++) {
            const int f = tid + it * 256;
            const int r = f >> 5;
            const int d4 = (f & 31) * 4;
            const float4 kv = *(const float4*)(Kg + (size_t)r * HD_ + d4);
            sKt[(d4 + 0) * 68 + r] = kv.x;
            sKt[(d4 + 1) * 68 + r] = kv.y;
            sKt[(d4 + 2) * 68 + r] = kv.z;
            sKt[(d4 + 3) * 68 + r] = kv.w;
            *(float4*)&sV[r * 128 + d4] = *(const float4*)(Vg + (size_t)r * HD_ + d4);
        }
        __syncthreads();

        float sacc[4][4];
#pragma unroll
        for (int i = 0; i < 4; i++)
#pragma unroll
            for (int j = 0; j < 4; j++) sacc[i][j] = 0.f;

#pragma unroll 8
        for (int d = 0; d < 128; d++) {
            const float4 a = *(const float4*)&sQt[d * 68 + ty * 4];
            const float4 kk = *(const float4*)&sKt[d * 68 + tx * 4];
            const float av[4] = {a.x, a.y, a.z, a.w};
            const float kv2[4] = {kk.x, kk.y, kk.z, kk.w};
#pragma unroll
            for (int i = 0; i < 4; i++)
#pragma unroll
                for (int j = 0; j < 4; j++)
                    sacc[i][j] = fmaf(av[i], kv2[j], sacc[i][j]);
        }

        const int rq0 = qt * 64 + ty * 4;
        const int ck0 = kt * 64 + tx * 4;
        float corr[4];
#pragma unroll
        for (int i = 0; i < 4; i++) {
            float sv[4];
#pragma unroll
            for (int j = 0; j < 4; j++)
                sv[j] = (ck0 + j <= rq0 + i) ? sacc[i][j] * scale : -1e30f;
            float rm = fmaxf(fmaxf(sv[0], sv[1]), fmaxf(sv[2], sv[3]));
#pragma unroll
            for (int msk = 8; msk; msk >>= 1)
                rm = fmaxf(rm, __shfl_xor_sync(0xffffffffu, rm, msk, 16));
            const float newm = fmaxf(mi[i], rm);
            corr[i] = __expf(mi[i] - newm);
            float rs = 0.f;
#pragma unroll
            for (int j = 0; j < 4; j++) {
                const float pz = __expf(sv[j] - newm);
                rs += pz;
                sPt[(tx * 4 + j) * 68 + ty * 4 + i] = pz;
            }
#pragma unroll
            for (int msk = 8; msk; msk >>= 1)
                rs += __shfl_xor_sync(0xffffffffu, rs, msk, 16);
            li[i] = li[i] * corr[i] + rs;
            mi[i] = newm;
        }
        __syncthreads();

#pragma unroll
        for (int i = 0; i < 4; i++)
#pragma unroll
            for (int j = 0; j < 8; j++) O[i][j] *= corr[i];

#pragma unroll 4
        for (int c = 0; c < 64; c++) {
            const float4 p = *(const float4*)&sPt[c * 68 + ty * 4];
            const float4 v0 = *(const float4*)&sV[c * 128 + tx * 4];
            const float4 v1 = *(const float4*)&sV[c * 128 + 64 + tx * 4];
            const float pv[4] = {p.x, p.y, p.z, p.w};
            const float va[8] = {v0.x, v0.y, v0.z, v0.w, v1.x, v1.y, v1.z, v1.w};
#pragma unroll
            for (int i = 0; i < 4; i++)
#pragma unroll
                for (int j = 0; j < 8; j++)
                    O[i][j] = fmaf(pv[i], va[j], O[i][j]);
        }
    }

#pragma unroll
    for (int i = 0; i < 4; i++) {
        const float inv = 1.f / li[i];
        const int srow = qt * 64 + ty * 4 + i;
        float* dst = g_ctx + ((size_t)b * S_ + srow) * HID_ + h * HD_;
#pragma unroll
        for (int j = 0; j < 4; j++) dst[tx * 4 + j] = O[i][j] * inv;
#pragma unroll
        for (int j = 0; j < 4; j++) dst[64 + tx * 4 + j] = O[i][j + 4] * inv;
    }
}

// ---------------------------------------------------------------------------
// Inputs: hidden_states, attention_mask(analytic causal), cos, sin,
//         Wq, Wkv, Wd, bd
// ---------------------------------------------------------------------------
extern "C" void kernel_launch(void* const* d_in, const int* in_sizes, int n_in,
                              void* d_out, int out_size)
{
    (void)in_sizes; (void)n_in; (void)out_size;
    const float* hidden = (const float*)d_in[0];
    const float* cosT   = (const float*)d_in[2];
    const float* sinT   = (const float*)d_in[3];
    const float* Wq     = (const float*)d_in[4];
    const float* Wkv    = (const float*)d_in[5];
    const float* Wd     = (const float*)d_in[6];
    const float* bd     = (const float*)d_in[7];
    float* out = (float*)d_out;

    cudaFuncSetAttribute(attn_kernel,
                         cudaFuncAttributeMaxDynamicSharedMemorySize, ATTN_SMEM_BYTES);
    cudaFuncSetAttribute(gemm_h3<0>,
                         cudaFuncAttributeMaxDynamicSharedMemorySize, SM3);
    cudaFuncSetAttribute(gemm_h3<1>,
                         cudaFuncAttributeMaxDynamicSharedMemorySize, SM3);
    cudaFuncSetAttribute(gemm_h1,
                         cudaFuncAttributeMaxDynamicSharedMemorySize, SM1);

    const int M = B_ * S_;

    {
        int n4 = (B_ * S_ * HID_) / 4;
        split2_sel<<<(n4 + 255) / 256, 256>>>(hidden, 0, n4);
        n4 = (HID_ * HID_) / 4;
        split2_sel<<<(n4 + 255) / 256, 256>>>(Wq, 1, n4);
        n4 = (2 * NKV_ * HD_ * HID_) / 4;
        split2_sel<<<(n4 + 255) / 256, 256>>>(Wkv, 2, n4);
        n4 = (HID_ * HID_) / 4;
        split1_sel<<<(n4 + 255) / 256, 256>>>(Wd, 0, n4);
    }

    gemm_h3<0><<<dim3(HID_ / 128, M / 128), 256, SM3>>>();
    gemm_h3<1><<<dim3((2 * NKV_ * HD_) / 128, M / 128), 256, SM3>>>();

    const int totalPairs = B_ * NH_ * S_ * (HD_ / 2) + B_ * NKV_ * S_ * (HD_ / 2);
    rope_kernel<<<(totalPairs + 255) / 256, 256>>>(cosT, sinT);

    attn_kernel<<<dim3(S_ / 64, NH_, B_), 256, ATTN_SMEM_BYTES>>>();

    {
        const int n4 = (B_ * S_ * HID_) / 4;
        split1_sel<<<(n4 + 255) / 256, 256>>>(nullptr, 1, n4);
    }
    gemm_h1<<<dim3(HID_ / 128, M / 128), 256, SM1>>>(bd, out);
}